// round 1
// baseline (speedup 1.0000x reference)
#include <cuda_runtime.h>

// ---------------------------------------------------------------------------
// QuanvolutionFilter: 4-qubit circuit per 2x2 patch, reformulated as
//   out_k(patch) = sum_t C_k[t] * prod_w u_w(t_w),  u_w = (1, cos a_w, sin a_w)
// where C (4 x 81) is precomputed on-device from ansatz_params, W, b.
// ---------------------------------------------------------------------------

__device__ float g_C[324]; // layout [t][k], t in 0..80, k in 0..3

struct cplx { float x, y; };
__device__ __forceinline__ cplx cmul(cplx a, cplx b) {
    return { a.x * b.x - a.y * b.y, a.x * b.y + a.y * b.x };
}
__device__ __forceinline__ cplx cadd(cplx a, cplx b) { return { a.x + b.x, a.y + b.y }; }

#define NW 4
#define NL 3

// One-block setup: build U (16x16), A_k = sum_w W[k,w] Re(U^dag Z_w U),
// then basis-change to the (1,cos,sin)^{x4} tensor coefficients C.
__global__ void setup_kernel(const float* __restrict__ params,
                             const float* __restrict__ W,
                             const float* __restrict__ bias) {
    __shared__ cplx U[16][16];       // U[row][col]
    __shared__ float A[4 * 256];     // A[k][i][j]
    __shared__ float zwk[4][16];     // sum_w W[k,w] * z_w(b)
    int tid = threadIdx.x;           // 256 threads

    // U = I
    {
        int r = tid >> 4, c = tid & 15;
        U[r][c] = { (r == c) ? 1.f : 0.f, 0.f };
    }
    __syncthreads();

    for (int l = 0; l < NL; l++) {
        // Rot(phi,theta,omega) on each wire
        for (int w = 0; w < NW; w++) {
            float phi = params[(l * NW + w) * 3 + 0];
            float th  = params[(l * NW + w) * 3 + 1];
            float om  = params[(l * NW + w) * 3 + 2];
            float ch = cosf(0.5f * th), sh = sinf(0.5f * th);
            float al = 0.5f * (phi + om), be = 0.5f * (phi - om);
            float ca = cosf(al), sa = sinf(al);
            float cb = cosf(be), sb = sinf(be);
            cplx g00 = {  ch * ca, -ch * sa };
            cplx g01 = { -sh * cb, -sh * sb };
            cplx g10 = {  sh * cb, -sh * sb };
            cplx g11 = {  ch * ca,  ch * sa };
            int pos = 3 - w;
            int m = 1 << pos;
            if (tid < 128) {
                int col = tid & 15, pidx = tid >> 4;   // 8 row-pairs x 16 cols
                int low  = pidx & (m - 1);
                int high = pidx >> pos;
                int i = (high << (pos + 1)) | low;     // bit_w(i) = 0
                int j = i | m;
                cplx ui = U[i][col], uj = U[j][col];
                U[i][col] = cadd(cmul(g00, ui), cmul(g01, uj));
                U[j][col] = cadd(cmul(g10, ui), cmul(g11, uj));
            }
            __syncthreads();
        }
        // CNOT ring with range r
        int rr_range = (l % (NW - 1)) + 1;
        for (int w = 0; w < NW; w++) {
            int tgt = (w + rr_range) % NW;
            int cm = 1 << (3 - w), tm = 1 << (3 - tgt);
            if (tid < 64) {
                int col = tid & 15, pi = tid >> 4;     // 4 swap-pairs x 16 cols
                int cnt = -1, row = 0;
                for (int r2 = 0; r2 < 16; r2++) {
                    if ((r2 & cm) && !(r2 & tm)) {
                        cnt++;
                        if (cnt == pi) { row = r2; break; }
                    }
                }
                int j = row | tm;
                cplx t0 = U[row][col], t1 = U[j][col];
                U[row][col] = t1;
                U[j][col]   = t0;
            }
            __syncthreads();
        }
    }

    // zwk[k][b] = sum_w W[k,w] * (1 - 2*bit_w(b))
    if (tid < 64) {
        int k = tid >> 4, bb = tid & 15;
        float s = 0.f;
        for (int w = 0; w < NW; w++) {
            float z = ((bb >> (3 - w)) & 1) ? -1.f : 1.f;
            s += W[k * 4 + w] * z;
        }
        zwk[k][bb] = s;
    }
    __syncthreads();

    // A[k][i][j] = sum_b zwk[k][b] * Re( conj(U[b][i]) * U[b][j] )
    for (int idx = tid; idx < 1024; idx += 256) {
        int k = idx >> 8, ij = idx & 255, i = ij >> 4, j = ij & 15;
        float s = 0.f;
        #pragma unroll
        for (int bb = 0; bb < 16; bb++) {
            float re = U[bb][i].x * U[bb][j].x + U[bb][i].y * U[bb][j].y;
            s += zwk[k][bb] * re;
        }
        A[idx] = s;
    }
    __syncthreads();

    // Basis change: per wire, q(i)q(j) in {c^2, cs, s^2} expressed over (1, cos, sin):
    //   t=0 ('1')  : (0,0)->+ , (1,1)->+
    //   t=1 ('cos'): (0,0)->+ , (1,1)->-
    //   t=2 ('sin'): (0,1)->+ , (1,0)->+
    // all with factor 0.5 per wire -> 1/16 overall.
    for (int idx = tid; idx < 324; idx += 256) {
        int t_idx = idx >> 2, k = idx & 3;
        int tw[4];
        tw[3] = t_idx % 3;
        tw[2] = (t_idx / 3) % 3;
        tw[1] = (t_idx / 9) % 3;
        tw[0] = t_idx / 27;
        float sum = 0.f;
        for (int combo = 0; combo < 16; combo++) {
            int i = 0, j = 0;
            float sign = 1.f;
            #pragma unroll
            for (int w = 0; w < 4; w++) {
                int c = (combo >> w) & 1;
                int t = tw[w];
                int iw, jw;
                if (t == 0)      { iw = c; jw = c; }
                else if (t == 1) { iw = c; jw = c; if (c) sign = -sign; }
                else             { iw = c; jw = 1 - c; }
                i |= iw << (3 - w);
                j |= jw << (3 - w);
            }
            sum += sign * A[k * 256 + i * 16 + j];
        }
        float val = sum * (1.f / 16.f);
        if (t_idx == 0) val += bias[k];
        g_C[t_idx * 4 + k] = val;
    }
}

// Main kernel: one thread per patch.
__global__ void __launch_bounds__(256) quanv_kernel(const float* __restrict__ x,
                                                    float* __restrict__ out,
                                                    int nPatches) {
    __shared__ float4 C4[81];
    {
        float* Cs = (float*)C4;
        for (int i = threadIdx.x; i < 324; i += 256) Cs[i] = g_C[i];
    }
    __syncthreads();

    int p = blockIdx.x * blockDim.x + threadIdx.x;
    if (p >= nPatches) return;

    int b  = p / 196;
    int q  = p - b * 196;
    int py = q / 14;
    int px = q - py * 14;

    const float* base = x + b * 784 + py * 56 + px * 2;
    float2 r0 = *(const float2*)base;          // img[2py][2px], img[2py][2px+1]
    float2 r1 = *(const float2*)(base + 28);   // img[2py+1][2px], img[2py+1][2px+1]

    float c0, s0, c1, s1, c2, s2, c3, s3;
    __sincosf(r0.x, &s0, &c0);
    __sincosf(r0.y, &s1, &c1);
    __sincosf(r1.x, &s2, &c2);
    __sincosf(r1.y, &s3, &c3);

    float p01[9] = { 1.f, c1, s1, c0, c0 * c1, c0 * s1, s0, s0 * c1, s0 * s1 };
    float p23[9] = { 1.f, c3, s3, c2, c2 * c3, c2 * s3, s2, s2 * c3, s2 * s3 };

    float a0 = 0.f, a1 = 0.f, a2 = 0.f, a3 = 0.f;
    #pragma unroll
    for (int ia = 0; ia < 9; ia++) {
        #pragma unroll
        for (int ib = 0; ib < 9; ib++) {
            float vv = p01[ia] * p23[ib];
            float4 cc = C4[ia * 9 + ib];
            a0 = fmaf(cc.x, vv, a0);
            a1 = fmaf(cc.y, vv, a1);
            a2 = fmaf(cc.z, vv, a2);
            a3 = fmaf(cc.w, vv, a3);
        }
    }
    ((float4*)out)[p] = make_float4(a0, a1, a2, a3);
}

extern "C" void kernel_launch(void* const* d_in, const int* in_sizes, int n_in,
                              void* d_out, int out_size) {
    const float* x      = (const float*)d_in[0];
    const float* params = (const float*)d_in[1];
    const float* W      = (const float*)d_in[2];
    const float* bias   = (const float*)d_in[3];

    int nPatches = in_sizes[0] / 4; // B*784/4 = B*196

    setup_kernel<<<1, 256>>>(params, W, bias);
    quanv_kernel<<<(nPatches + 255) / 256, 256>>>(x, (float*)d_out, nPatches);
}

// round 2
// speedup vs baseline: 1.2662x; 1.2662x over previous
#include <cuda_runtime.h>

// ---------------------------------------------------------------------------
// QuanvolutionFilter: 4-qubit circuit per 2x2 patch, reformulated as
//   out_k(patch) = sum_t C_k[t] * prod_w u_w(t_w),  u_w = (1, cos a_w, sin a_w)
// C (81 x 4) precomputed on-device from ansatz_params, W, b.
// Main kernel: 4 patches/thread, f32x2 packed FMA, coeffs in shared as u64x2.
// ---------------------------------------------------------------------------

__device__ float g_C[324]; // layout [t][k], t in 0..80, k in 0..3

struct cplx { float x, y; };

#define NW 4
#define NL 3

// Setup: warp-0 lanes 0..15 build U (column per lane, rows in registers, no
// syncs), then 256 threads compute A_k = sum_w W[k,w] Re(U^dag Z_w U) and the
// (1,cos,sin)^{x4} tensor coefficients C.
__global__ void setup_kernel(const float* __restrict__ params,
                             const float* __restrict__ W,
                             const float* __restrict__ bias) {
    __shared__ cplx U[16][16];       // U[row][col]
    __shared__ float A[4 * 256];     // A[k][i][j]
    __shared__ float zwk[4][16];     // sum_w W[k,w] * z_w(b)
    int tid = threadIdx.x;           // 256 threads

    if (tid < 16) {
        const int col = tid;
        float ur[16], ui[16];
        #pragma unroll
        for (int r = 0; r < 16; r++) { ur[r] = (r == col) ? 1.f : 0.f; ui[r] = 0.f; }

        float P[36];
        #pragma unroll
        for (int i = 0; i < 36; i++) P[i] = params[i];

        #pragma unroll
        for (int l = 0; l < NL; l++) {
            // Rot(phi,theta,omega) per wire: in-register row-pair mixes
            #pragma unroll
            for (int w = 0; w < NW; w++) {
                float phi = P[(l * NW + w) * 3 + 0];
                float th  = P[(l * NW + w) * 3 + 1];
                float om  = P[(l * NW + w) * 3 + 2];
                float ch, sh, ca, sa, cb, sb;
                __sincosf(0.5f * th, &sh, &ch);
                __sincosf(0.5f * (phi + om), &sa, &ca);
                __sincosf(0.5f * (phi - om), &sb, &cb);
                float g00r =  ch * ca, g00i = -ch * sa;
                float g01r = -sh * cb, g01i = -sh * sb;
                float g10r =  sh * cb, g10i = -sh * sb;
                float g11r =  ch * ca, g11i =  ch * sa;
                const int m = 1 << (3 - w);
                #pragma unroll
                for (int i = 0; i < 16; i++) {
                    if (!(i & m)) {
                        const int j = i | m;
                        float xr = ur[i], xi = ui[i], yr = ur[j], yi = ui[j];
                        ur[i] = g00r * xr - g00i * xi + g01r * yr - g01i * yi;
                        ui[i] = g00r * xi + g00i * xr + g01r * yi + g01i * yr;
                        ur[j] = g10r * xr - g10i * xi + g11r * yr - g11i * yi;
                        ui[j] = g10r * xi + g10i * xr + g11r * yi + g11i * yr;
                    }
                }
            }
            // CNOT ring, range rng: pure register swaps, fully unrolled
            const int rng = (l % (NW - 1)) + 1;
            #pragma unroll
            for (int w = 0; w < NW; w++) {
                const int tgt = (w + rng) % NW;
                const int cm = 1 << (3 - w), tm = 1 << (3 - tgt);
                #pragma unroll
                for (int i = 0; i < 16; i++) {
                    if ((i & cm) && !(i & tm)) {
                        const int j = i | tm;
                        float tr = ur[i], ti = ui[i];
                        ur[i] = ur[j]; ui[i] = ui[j];
                        ur[j] = tr;    ui[j] = ti;
                    }
                }
            }
        }
        #pragma unroll
        for (int r = 0; r < 16; r++) U[r][col] = { ur[r], ui[r] };
    }

    // zwk on a different warp, concurrent with the U build
    if (tid >= 64 && tid < 128) {
        int k = (tid - 64) >> 4, bb = tid & 15;
        float s = 0.f;
        #pragma unroll
        for (int w = 0; w < NW; w++) {
            float z = ((bb >> (3 - w)) & 1) ? -1.f : 1.f;
            s += W[k * 4 + w] * z;
        }
        zwk[k][bb] = s;
    }
    __syncthreads();

    // A[k][i][j] = sum_b zwk[k][b] * Re( conj(U[b][i]) * U[b][j] )
    for (int idx = tid; idx < 1024; idx += 256) {
        int k = idx >> 8, ij = idx & 255, i = ij >> 4, j = ij & 15;
        float s = 0.f;
        #pragma unroll
        for (int bb = 0; bb < 16; bb++) {
            float re = U[bb][i].x * U[bb][j].x + U[bb][i].y * U[bb][j].y;
            s += zwk[k][bb] * re;
        }
        A[idx] = s;
    }
    __syncthreads();

    // Basis change: per wire, q(i)q(j) in {c^2, cs, s^2} over (1, cos, sin);
    // factor 0.5 per wire -> 1/16 overall. Bias folded into constant term.
    for (int idx = tid; idx < 324; idx += 256) {
        int t_idx = idx >> 2, k = idx & 3;
        int tw[4];
        tw[3] = t_idx % 3;
        tw[2] = (t_idx / 3) % 3;
        tw[1] = (t_idx / 9) % 3;
        tw[0] = t_idx / 27;
        float sum = 0.f;
        for (int combo = 0; combo < 16; combo++) {
            int i = 0, j = 0;
            float sign = 1.f;
            #pragma unroll
            for (int w = 0; w < 4; w++) {
                int c = (combo >> w) & 1;
                int t = tw[w];
                int iw, jw;
                if (t == 0)      { iw = c; jw = c; }
                else if (t == 1) { iw = c; jw = c; if (c) sign = -sign; }
                else             { iw = c; jw = 1 - c; }
                i |= iw << (3 - w);
                j |= jw << (3 - w);
            }
            sum += sign * A[k * 256 + i * 16 + j];
        }
        float val = sum * (1.f / 16.f);
        if (t_idx == 0) val += bias[k];
        g_C[t_idx * 4 + k] = val;
    }
}

__device__ __forceinline__ unsigned long long splat2(float v) {
    unsigned long long r;
    unsigned int vi = __float_as_uint(v);
    asm("mov.b64 %0, {%1, %1};" : "=l"(r) : "r"(vi));
    return r;
}

// Main kernel: 4 patches per thread (strided by nPatches/4), packed f32x2 FMA.
__global__ void __launch_bounds__(256) quanv_kernel(const float* __restrict__ x,
                                                    float* __restrict__ out,
                                                    int quarter) {
    __shared__ ulonglong2 C2[81];   // per t: {C0,C1} packed, {C2,C3} packed
    {
        const float4* Cg = (const float4*)g_C;
        for (int i = threadIdx.x; i < 81; i += 256) {
            float4 c = Cg[i];
            ulonglong2 u;
            asm("mov.b64 %0, {%1, %2};" : "=l"(u.x)
                : "r"(__float_as_uint(c.x)), "r"(__float_as_uint(c.y)));
            asm("mov.b64 %0, {%1, %2};" : "=l"(u.y)
                : "r"(__float_as_uint(c.z)), "r"(__float_as_uint(c.w)));
            C2[i] = u;
        }
    }
    __syncthreads();

    int t = blockIdx.x * 256 + threadIdx.x;
    if (t >= quarter) return;

    float p01[4][9], p23[4][9];
    #pragma unroll
    for (int pp = 0; pp < 4; pp++) {
        int p  = t + pp * quarter;
        int b  = p / 196;
        int q  = p - b * 196;
        int py = q / 14;
        int px = q - py * 14;
        const float* base = x + b * 784 + py * 56 + px * 2;
        float2 r0 = *(const float2*)base;
        float2 r1 = *(const float2*)(base + 28);
        float c0, s0, c1, s1, c2, s2, c3, s3;
        __sincosf(r0.x, &s0, &c0);
        __sincosf(r0.y, &s1, &c1);
        __sincosf(r1.x, &s2, &c2);
        __sincosf(r1.y, &s3, &c3);
        p01[pp][0] = 1.f;     p01[pp][1] = c1;      p01[pp][2] = s1;
        p01[pp][3] = c0;      p01[pp][4] = c0 * c1; p01[pp][5] = c0 * s1;
        p01[pp][6] = s0;      p01[pp][7] = s0 * c1; p01[pp][8] = s0 * s1;
        p23[pp][0] = 1.f;     p23[pp][1] = c3;      p23[pp][2] = s3;
        p23[pp][3] = c2;      p23[pp][4] = c2 * c3; p23[pp][5] = c2 * s3;
        p23[pp][6] = s2;      p23[pp][7] = s2 * c3; p23[pp][8] = s2 * s3;
    }

    unsigned long long acc01[4] = {0ull, 0ull, 0ull, 0ull};
    unsigned long long acc23[4] = {0ull, 0ull, 0ull, 0ull};

    #pragma unroll
    for (int ia = 0; ia < 9; ia++) {
        #pragma unroll
        for (int ib = 0; ib < 9; ib++) {
            ulonglong2 cc = C2[ia * 9 + ib];
            #pragma unroll
            for (int pp = 0; pp < 4; pp++) {
                float vv = p01[pp][ia] * p23[pp][ib];
                unsigned long long vs = splat2(vv);
                asm("fma.rn.f32x2 %0, %1, %2, %0;"
                    : "+l"(acc01[pp]) : "l"(cc.x), "l"(vs));
                asm("fma.rn.f32x2 %0, %1, %2, %0;"
                    : "+l"(acc23[pp]) : "l"(cc.y), "l"(vs));
            }
        }
    }

    #pragma unroll
    for (int pp = 0; pp < 4; pp++) {
        int p = t + pp * quarter;
        unsigned int a0, a1, a2, a3;
        asm("mov.b64 {%0, %1}, %2;" : "=r"(a0), "=r"(a1) : "l"(acc01[pp]));
        asm("mov.b64 {%0, %1}, %2;" : "=r"(a2), "=r"(a3) : "l"(acc23[pp]));
        ((float4*)out)[p] = make_float4(__uint_as_float(a0), __uint_as_float(a1),
                                        __uint_as_float(a2), __uint_as_float(a3));
    }
}

extern "C" void kernel_launch(void* const* d_in, const int* in_sizes, int n_in,
                              void* d_out, int out_size) {
    const float* x      = (const float*)d_in[0];
    const float* params = (const float*)d_in[1];
    const float* W      = (const float*)d_in[2];
    const float* bias   = (const float*)d_in[3];

    int nPatches = in_sizes[0] / 4;   // B*196
    int quarter  = nPatches / 4;      // 196 divisible by 4 -> exact

    setup_kernel<<<1, 256>>>(params, W, bias);
    quanv_kernel<<<(quarter + 255) / 256, 256>>>(x, (float*)d_out, quarter);
}

// round 3
// speedup vs baseline: 2.0026x; 1.5815x over previous
#include <cuda_runtime.h>

typedef unsigned long long u64;

// ---------------------------------------------------------------------------
// QuanvolutionFilter reformulated:
//   out_k(patch) = sum_{ia,ib} C_k[ia,ib] * p01[ia] * p23[ib],
//   p01/p23 = (1,cos,sin) tensor factors of wire pairs (0,1) and (2,3).
// C precomputed on-device; stored DUPLICATED per 32-bit half so the main
// kernel can pack TWO PATCHES per f32x2 lane pair (no splats needed).
// ---------------------------------------------------------------------------

__device__ __align__(16) u64 g_Cd[324]; // [t][k], each u64 = {C,C} duplicated

struct cplx { float x, y; };

#define NW 4
#define NL 3

__global__ void setup_kernel(const float* __restrict__ params,
                             const float* __restrict__ W,
                             const float* __restrict__ bias) {
    __shared__ float G[12][8];        // per-gate 2x2 complex coeffs
    __shared__ cplx U[16][16];        // U[row][col]
    __shared__ float A[4 * 256];      // A[k][i][j]
    __shared__ float zwk[4][16];
    int tid = threadIdx.x;            // 256 threads

    // Precompute all 12 Rot gate coefficient sets in parallel (full precision)
    if (tid < 12) {
        float phi = params[tid * 3 + 0];
        float th  = params[tid * 3 + 1];
        float om  = params[tid * 3 + 2];
        float ch = cosf(0.5f * th), sh = sinf(0.5f * th);
        float al = 0.5f * (phi + om), be = 0.5f * (phi - om);
        float ca = cosf(al), sa = sinf(al);
        float cb = cosf(be), sb = sinf(be);
        G[tid][0] =  ch * ca; G[tid][1] = -ch * sa;   // g00
        G[tid][2] = -sh * cb; G[tid][3] = -sh * sb;   // g01
        G[tid][4] =  sh * cb; G[tid][5] = -sh * sb;   // g10
        G[tid][6] =  ch * ca; G[tid][7] =  ch * sa;   // g11
    }
    // U = I
    { int r = tid >> 4, c = tid & 15; U[r][c] = { (r == c) ? 1.f : 0.f, 0.f }; }
    // zwk[k][b] = sum_w W[k,w] * (1 - 2*bit_w(b))  (parallel with gate calc)
    if (tid >= 128 && tid < 192) {
        int k = (tid - 128) >> 4, bb = tid & 15;
        float s = 0.f;
        #pragma unroll
        for (int w = 0; w < NW; w++) {
            float z = ((bb >> (3 - w)) & 1) ? -1.f : 1.f;
            s += W[k * 4 + w] * z;
        }
        zwk[k][bb] = s;
    }
    __syncthreads();

    for (int l = 0; l < NL; l++) {
        for (int w = 0; w < NW; w++) {
            if (tid < 128) {
                const float* g = G[l * 4 + w];
                float g00r = g[0], g00i = g[1], g01r = g[2], g01i = g[3];
                float g10r = g[4], g10i = g[5], g11r = g[6], g11i = g[7];
                int pos = 3 - w, m = 1 << pos;
                int col = tid & 15, pidx = tid >> 4;
                int low  = pidx & (m - 1);
                int high = pidx >> pos;
                int i = (high << (pos + 1)) | low;
                int j = i | m;
                cplx ui = U[i][col], uj = U[j][col];
                U[i][col] = { g00r * ui.x - g00i * ui.y + g01r * uj.x - g01i * uj.y,
                              g00r * ui.y + g00i * ui.x + g01r * uj.y + g01i * uj.x };
                U[j][col] = { g10r * ui.x - g10i * ui.y + g11r * uj.x - g11i * uj.y,
                              g10r * ui.y + g10i * ui.x + g11r * uj.y + g11i * uj.x };
            }
            __syncthreads();
        }
        int rng = (l % (NW - 1)) + 1;
        for (int w = 0; w < NW; w++) {
            int tgt = (w + rng) % NW;
            int cm = 1 << (3 - w), tm = 1 << (3 - tgt);
            if (tid < 64) {
                int col = tid & 15, pi = tid >> 4;
                int cnt = -1, row = 0;
                for (int r2 = 0; r2 < 16; r2++) {
                    if ((r2 & cm) && !(r2 & tm)) {
                        cnt++;
                        if (cnt == pi) { row = r2; break; }
                    }
                }
                int j = row | tm;
                cplx t0 = U[row][col], t1 = U[j][col];
                U[row][col] = t1;
                U[j][col]   = t0;
            }
            __syncthreads();
        }
    }

    // A[k][i][j] = sum_b zwk[k][b] * Re( conj(U[b][i]) * U[b][j] )
    for (int idx = tid; idx < 1024; idx += 256) {
        int k = idx >> 8, ij = idx & 255, i = ij >> 4, j = ij & 15;
        float s = 0.f;
        #pragma unroll
        for (int bb = 0; bb < 16; bb++) {
            float re = U[bb][i].x * U[bb][j].x + U[bb][i].y * U[bb][j].y;
            s += zwk[k][bb] * re;
        }
        A[idx] = s;
    }
    __syncthreads();

    // Basis change to (1,cos,sin)^{x4}; factor 1/16, bias in constant term.
    for (int idx = tid; idx < 324; idx += 256) {
        int t_idx = idx >> 2, k = idx & 3;
        int tw[4];
        tw[3] = t_idx % 3;
        tw[2] = (t_idx / 3) % 3;
        tw[1] = (t_idx / 9) % 3;
        tw[0] = t_idx / 27;
        float sum = 0.f;
        for (int combo = 0; combo < 16; combo++) {
            int i = 0, j = 0;
            float sign = 1.f;
            #pragma unroll
            for (int w = 0; w < 4; w++) {
                int c = (combo >> w) & 1;
                int t = tw[w];
                int iw, jw;
                if (t == 0)      { iw = c; jw = c; }
                else if (t == 1) { iw = c; jw = c; if (c) sign = -sign; }
                else             { iw = c; jw = 1 - c; }
                i |= iw << (3 - w);
                j |= jw << (3 - w);
            }
            sum += sign * A[k * 256 + i * 16 + j];
        }
        float val = sum * (1.f / 16.f);
        if (t_idx == 0) val += bias[k];
        unsigned int vi = __float_as_uint(val);
        g_Cd[t_idx * 4 + k] = (u64)vi | ((u64)vi << 32);
    }
}

// --------------------------- main kernel -----------------------------------

__device__ __forceinline__ u64 pack2(float lo, float hi) {
    u64 r;
    asm("mov.b64 %0, {%1, %2};" : "=l"(r)
        : "r"(__float_as_uint(lo)), "r"(__float_as_uint(hi)));
    return r;
}
__device__ __forceinline__ u64 mul2(u64 a, u64 b) {
    u64 r; asm("mul.rn.f32x2 %0, %1, %2;" : "=l"(r) : "l"(a), "l"(b)); return r;
}
__device__ __forceinline__ u64 fma2(u64 a, u64 b, u64 c) {
    u64 r; asm("fma.rn.f32x2 %0, %1, %2, %3;" : "=l"(r) : "l"(a), "l"(b), "l"(c));
    return r;
}

// 4 patches per thread = 2 f32x2 groups; coefficients duplicated in shared.
__global__ void __launch_bounds__(256) quanv_kernel(const float* __restrict__ x,
                                                    float* __restrict__ out,
                                                    int quarter) {
    __shared__ __align__(16) u64 Cs[324];   // [t][k] duplicated
    {
        const ulonglong2* src = (const ulonglong2*)g_Cd;
        ulonglong2* dst = (ulonglong2*)Cs;
        for (int i = threadIdx.x; i < 162; i += 256) dst[i] = src[i];
    }
    __syncthreads();

    int t = blockIdx.x * 256 + threadIdx.x;
    if (t >= quarter) return;

    u64 w0c[2], w0s[2], w1c[2], w1s[2];  // wires 0,1 trig packs per group
    u64 p23[2][9];                        // wires 2,3 tensor factors per group

    #pragma unroll
    for (int g = 0; g < 2; g++) {
        float cA[4], sA[4], cB[4], sB[4];
        {
            int p  = t + (2 * g) * quarter;
            int b  = p / 196, q = p - b * 196;
            int py = q / 14,  px = q - py * 14;
            const float* base = x + b * 784 + py * 56 + px * 2;
            float2 r0 = *(const float2*)base;
            float2 r1 = *(const float2*)(base + 28);
            __sincosf(r0.x, &sA[0], &cA[0]);
            __sincosf(r0.y, &sA[1], &cA[1]);
            __sincosf(r1.x, &sA[2], &cA[2]);
            __sincosf(r1.y, &sA[3], &cA[3]);
        }
        {
            int p  = t + (2 * g + 1) * quarter;
            int b  = p / 196, q = p - b * 196;
            int py = q / 14,  px = q - py * 14;
            const float* base = x + b * 784 + py * 56 + px * 2;
            float2 r0 = *(const float2*)base;
            float2 r1 = *(const float2*)(base + 28);
            __sincosf(r0.x, &sB[0], &cB[0]);
            __sincosf(r0.y, &sB[1], &cB[1]);
            __sincosf(r1.x, &sB[2], &cB[2]);
            __sincosf(r1.y, &sB[3], &cB[3]);
        }
        w0c[g] = pack2(cA[0], cB[0]); w0s[g] = pack2(sA[0], sB[0]);
        w1c[g] = pack2(cA[1], cB[1]); w1s[g] = pack2(sA[1], sB[1]);
        u64 c2p = pack2(cA[2], cB[2]), s2p = pack2(sA[2], sB[2]);
        u64 c3p = pack2(cA[3], cB[3]), s3p = pack2(sA[3], sB[3]);
        p23[g][0] = 0; // unused (factor == 1)
        p23[g][1] = c3p;            p23[g][2] = s3p;
        p23[g][3] = c2p;            p23[g][4] = mul2(c2p, c3p);
        p23[g][5] = mul2(c2p, s3p); p23[g][6] = s2p;
        p23[g][7] = mul2(s2p, c3p); p23[g][8] = mul2(s2p, s3p);
    }

    u64 acc[2][4];

    #pragma unroll
    for (int ia = 0; ia < 9; ia++) {
        // m[g][k] = sum_ib C_k[ia,ib] * p23[g][ib];   ib=0 term is just C.
        u64 m[2][4];
        {
            const ulonglong2* Cp = (const ulonglong2*)&Cs[(ia * 9) * 4];
            ulonglong2 c01 = Cp[0], c23 = Cp[1];
            #pragma unroll
            for (int g = 0; g < 2; g++) {
                m[g][0] = c01.x; m[g][1] = c01.y;
                m[g][2] = c23.x; m[g][3] = c23.y;
            }
        }
        #pragma unroll
        for (int ib = 1; ib < 9; ib++) {
            const ulonglong2* Cp = (const ulonglong2*)&Cs[(ia * 9 + ib) * 4];
            ulonglong2 c01 = Cp[0], c23 = Cp[1];
            #pragma unroll
            for (int g = 0; g < 2; g++) {
                m[g][0] = fma2(c01.x, p23[g][ib], m[g][0]);
                m[g][1] = fma2(c01.y, p23[g][ib], m[g][1]);
                m[g][2] = fma2(c23.x, p23[g][ib], m[g][2]);
                m[g][3] = fma2(c23.y, p23[g][ib], m[g][3]);
            }
        }
        // acc += p01[ia] * m;  p01 factor from {1,c0,s0} x {1,c1,s1}
        const int t0 = ia / 3, t1 = ia % 3;
        if (ia == 0) {
            #pragma unroll
            for (int g = 0; g < 2; g++)
                #pragma unroll
                for (int k = 0; k < 4; k++) acc[g][k] = m[g][k];
        } else {
            #pragma unroll
            for (int g = 0; g < 2; g++) {
                u64 pa;
                if (t0 == 0)      pa = (t1 == 1) ? w1c[g] : w1s[g];
                else if (t1 == 0) pa = (t0 == 1) ? w0c[g] : w0s[g];
                else              pa = mul2((t0 == 1) ? w0c[g] : w0s[g],
                                            (t1 == 1) ? w1c[g] : w1s[g]);
                #pragma unroll
                for (int k = 0; k < 4; k++)
                    acc[g][k] = fma2(pa, m[g][k], acc[g][k]);
            }
        }
    }

    #pragma unroll
    for (int g = 0; g < 2; g++) {
        unsigned int lo[4], hi[4];
        #pragma unroll
        for (int k = 0; k < 4; k++)
            asm("mov.b64 {%0, %1}, %2;" : "=r"(lo[k]), "=r"(hi[k]) : "l"(acc[g][k]));
        int pA = t + (2 * g) * quarter;
        int pB = t + (2 * g + 1) * quarter;
        ((float4*)out)[pA] = make_float4(__uint_as_float(lo[0]), __uint_as_float(lo[1]),
                                         __uint_as_float(lo[2]), __uint_as_float(lo[3]));
        ((float4*)out)[pB] = make_float4(__uint_as_float(hi[0]), __uint_as_float(hi[1]),
                                         __uint_as_float(hi[2]), __uint_as_float(hi[3]));
    }
}

extern "C" void kernel_launch(void* const* d_in, const int* in_sizes, int n_in,
                              void* d_out, int out_size) {
    const float* x      = (const float*)d_in[0];
    const float* params = (const float*)d_in[1];
    const float* W      = (const float*)d_in[2];
    const float* bias   = (const float*)d_in[3];

    int nPatches = in_sizes[0] / 4;   // B*196
    int quarter  = nPatches / 4;      // exact: 196 % 4 == 0

    setup_kernel<<<1, 256>>>(params, W, bias);
    quanv_kernel<<<(quarter + 255) / 256, 256>>>(x, (float*)d_out, quarter);
}